// round 1
// baseline (speedup 1.0000x reference)
#include <cuda_runtime.h>
#include <cstddef>

#define NTOK 4096
#define DMODEL 1024
#define VOCAB 50257

// Scratch (allocation-free contract): 5*16MB + 64MB = 144MB static.
__device__ float g_x[(size_t)NTOK * DMODEL];
__device__ float g_q[(size_t)NTOK * DMODEL];
__device__ float g_k[(size_t)NTOK * DMODEL];
__device__ float g_v[(size_t)NTOK * DMODEL];
__device__ float g_s[(size_t)NTOK * NTOK];
__device__ float g_o[(size_t)NTOK * DMODEL];

// ---------------------------------------------------------------------------
// Embedding gather: x[i,:] = E[tokens[i],:]
// ---------------------------------------------------------------------------
__global__ void gather_kernel(const int* __restrict__ tokens,
                              const float* __restrict__ E,
                              float* __restrict__ x) {
    int row = blockIdx.x;
    int t = tokens[row];
    const float4* src = reinterpret_cast<const float4*>(E + (size_t)t * DMODEL);
    float4* dst = reinterpret_cast<float4*>(x + (size_t)row * DMODEL);
    // DMODEL/4 = 256 float4 per row, 256 threads
    dst[threadIdx.x] = src[threadIdx.x];
}

// ---------------------------------------------------------------------------
// Tiled SGEMM. NT=true:  C[M,N] = alpha * A[M,K] @ B[N,K]^T (+ bias[N])
//              NT=false: C[M,N] = alpha * A[M,K] @ B[K,N]   (+ bias[N])
// BM=BN=128, BK=16, 256 threads, 8x8 micro-tile per thread.
// Assumes K % 16 == 0 and M % 128 == 0 (true for all call sites).
// ---------------------------------------------------------------------------
template <bool NT>
__global__ void sgemm_kernel(const float* __restrict__ A,
                             const float* __restrict__ B,
                             const float* __restrict__ bias,
                             float* __restrict__ C,
                             int M, int N, int K, float alpha) {
    constexpr int BM = 128, BN = 128, BK = 16, TM = 8, TN = 8;
    __shared__ float As[BK][BM + 1];
    __shared__ float Bs[BK][BN + 1];

    const int tid = threadIdx.x;          // 0..255
    const int tx = tid % 16;
    const int ty = tid / 16;
    const int m0 = blockIdx.y * BM;
    const int n0 = blockIdx.x * BN;

    float acc[TM][TN];
#pragma unroll
    for (int i = 0; i < TM; ++i)
#pragma unroll
        for (int j = 0; j < TN; ++j) acc[i][j] = 0.0f;

    for (int k0 = 0; k0 < K; k0 += BK) {
        // --- load A tile [BM x BK] -> As[k][m] ---
        {
            const int k = tid % BK;       // 0..15
            const int mb = tid / BK;      // 0..15
#pragma unroll
            for (int r = 0; r < 8; ++r) {
                const int mm = mb + r * 16;
                As[k][mm] = A[(size_t)(m0 + mm) * K + (k0 + k)];
            }
        }
        // --- load B tile -> Bs[k][n] ---
        if (NT) {
            const int k = tid % BK;
            const int nb = tid / BK;
#pragma unroll
            for (int r = 0; r < 8; ++r) {
                const int nn = nb + r * 16;
                const int gn = n0 + nn;
                Bs[k][nn] = (gn < N) ? B[(size_t)gn * K + (k0 + k)] : 0.0f;
            }
        } else {
            const int nn = tid % 128;
            const int kb = tid / 128;     // 0..1
            const int gn = n0 + nn;
#pragma unroll
            for (int r = 0; r < 8; ++r) {
                const int kk = kb + r * 2;
                Bs[kk][nn] = (gn < N) ? B[(size_t)(k0 + kk) * N + gn] : 0.0f;
            }
        }
        __syncthreads();

#pragma unroll
        for (int k = 0; k < BK; ++k) {
            float a[TM], b[TN];
#pragma unroll
            for (int i = 0; i < TM; ++i) a[i] = As[k][ty * TM + i];
#pragma unroll
            for (int j = 0; j < TN; ++j) b[j] = Bs[k][tx * TN + j];
#pragma unroll
            for (int i = 0; i < TM; ++i)
#pragma unroll
                for (int j = 0; j < TN; ++j) acc[i][j] = fmaf(a[i], b[j], acc[i][j]);
        }
        __syncthreads();
    }

#pragma unroll
    for (int i = 0; i < TM; ++i) {
        const int gm = m0 + ty * TM + i;
#pragma unroll
        for (int j = 0; j < TN; ++j) {
            const int gn = n0 + tx * TN + j;
            if (gn < N) {
                float v = acc[i][j] * alpha;
                if (bias) v += bias[gn];
                C[(size_t)gm * N + gn] = v;
            }
        }
    }
}

// ---------------------------------------------------------------------------
// Causal row softmax in place on the [NTOK, NTOK] score matrix.
// Row i: softmax over cols [0, i]; cols > i are zeroed.
// ---------------------------------------------------------------------------
__global__ void softmax_causal_kernel(float* __restrict__ S) {
    const int row = blockIdx.x;
    float* s = S + (size_t)row * NTOK;
    const int len = row + 1;
    __shared__ float red[256];
    const int t = threadIdx.x;

    // max
    float m = -1e30f;
    for (int j = t; j < len; j += 256) m = fmaxf(m, s[j]);
    red[t] = m;
    __syncthreads();
#pragma unroll
    for (int st = 128; st > 0; st >>= 1) {
        if (t < st) red[t] = fmaxf(red[t], red[t + st]);
        __syncthreads();
    }
    m = red[0];
    __syncthreads();

    // exp + sum
    float sum = 0.0f;
    for (int j = t; j < len; j += 256) {
        const float e = expf(s[j] - m);
        s[j] = e;
        sum += e;
    }
    red[t] = sum;
    __syncthreads();
#pragma unroll
    for (int st = 128; st > 0; st >>= 1) {
        if (t < st) red[t] += red[t + st];
        __syncthreads();
    }
    const float inv = 1.0f / red[0];
    __syncthreads();

    for (int j = t; j < len; j += 256) s[j] *= inv;
    // zero masked tail so A@V can run as a dense GEMM
    for (int j = len + t; j < NTOK; j += 256) s[j] = 0.0f;
}

// ---------------------------------------------------------------------------
// Launch
// ---------------------------------------------------------------------------
extern "C" void kernel_launch(void* const* d_in, const int* in_sizes, int n_in,
                              void* d_out, int out_size) {
    const int*   tokens = (const int*)d_in[0];
    const float* E  = (const float*)d_in[1];
    const float* Wq = (const float*)d_in[2];
    const float* bq = (const float*)d_in[3];
    const float* Wk = (const float*)d_in[4];
    const float* bk = (const float*)d_in[5];
    const float* Wv = (const float*)d_in[6];
    const float* bv = (const float*)d_in[7];
    const float* Wp = (const float*)d_in[8];
    const float* bp = (const float*)d_in[9];
    float* out = (float*)d_out;

    float *x, *q, *k, *v, *s, *o;
    cudaGetSymbolAddress((void**)&x, g_x);
    cudaGetSymbolAddress((void**)&q, g_q);
    cudaGetSymbolAddress((void**)&k, g_k);
    cudaGetSymbolAddress((void**)&v, g_v);
    cudaGetSymbolAddress((void**)&s, g_s);
    cudaGetSymbolAddress((void**)&o, g_o);

    const float inv_sqrt_d = 1.0f / 32.0f;  // 1/sqrt(1024)

    // x = E[tokens]
    gather_kernel<<<NTOK, 256>>>(tokens, E, x);

    // Q/K/V = x @ W^T + b   (NT GEMMs, M=4096, N=1024, K=1024)
    {
        dim3 grid(DMODEL / 128, NTOK / 128);
        sgemm_kernel<true><<<grid, 256>>>(x, Wq, bq, q, NTOK, DMODEL, DMODEL, 1.0f);
        sgemm_kernel<true><<<grid, 256>>>(x, Wk, bk, k, NTOK, DMODEL, DMODEL, 1.0f);
        sgemm_kernel<true><<<grid, 256>>>(x, Wv, bv, v, NTOK, DMODEL, DMODEL, 1.0f);
    }

    // S = Q @ K^T / sqrt(d)   (NT, M=N=4096, K=1024)
    {
        dim3 grid(NTOK / 128, NTOK / 128);
        sgemm_kernel<true><<<grid, 256>>>(q, k, nullptr, s, NTOK, NTOK, DMODEL, inv_sqrt_d);
    }

    // causal softmax in place
    softmax_causal_kernel<<<NTOK, 256>>>(s);

    // O = A @ V   (NN, M=4096, N=1024, K=4096)
    {
        dim3 grid(DMODEL / 128, NTOK / 128);
        sgemm_kernel<false><<<grid, 256>>>(s, v, nullptr, o, NTOK, DMODEL, NTOK, 1.0f);
    }

    // logits = O @ Wp^T + bp   (NT, M=4096, N=50257, K=1024)
    {
        dim3 grid((VOCAB + 127) / 128, NTOK / 128);
        sgemm_kernel<true><<<grid, 256>>>(o, Wp, bp, out, NTOK, VOCAB, DMODEL, 1.0f);
    }
}

// round 4
// speedup vs baseline: 4.4472x; 4.4472x over previous
#include <cuda_runtime.h>
#include <cstdint>
#include <cstddef>

#define NTOK 4096
#define DMODEL 1024
#define VOCAB 50257

// Scratch (allocation-free contract)
__device__ float g_x [(size_t)NTOK * DMODEL];
__device__ float g_q [(size_t)NTOK * DMODEL];
__device__ float g_k [(size_t)NTOK * DMODEL];
__device__ float g_vt[(size_t)NTOK * DMODEL];   // V^T: [DMODEL, NTOK]
__device__ float g_s [(size_t)NTOK * NTOK];
__device__ float g_o [(size_t)NTOK * DMODEL];

// round-to-nearest tf32 (unbiased; result exactly representable in fp32)
__device__ __forceinline__ float tf32r(float x) {
    uint32_t u;
    asm("cvt.rna.tf32.f32 %0, %1;" : "=r"(u) : "f"(x));
    return __uint_as_float(u);
}
__device__ __forceinline__ float4 tf32r4(float4 v) {
    return make_float4(tf32r(v.x), tf32r(v.y), tf32r(v.z), tf32r(v.w));
}
__device__ __forceinline__ float4 sub4(float4 a, float4 b) {
    return make_float4(a.x - b.x, a.y - b.y, a.z - b.z, a.w - b.w);
}

__device__ __forceinline__ void mma16n8k8(float* d, const float* a, const float* b) {
    asm volatile(
        "mma.sync.aligned.m16n8k8.row.col.f32.tf32.tf32.f32 "
        "{%0,%1,%2,%3}, {%4,%5,%6,%7}, {%8,%9}, {%0,%1,%2,%3};"
        : "+f"(d[0]), "+f"(d[1]), "+f"(d[2]), "+f"(d[3])
        : "r"(__float_as_uint(a[0])), "r"(__float_as_uint(a[1])),
          "r"(__float_as_uint(a[2])), "r"(__float_as_uint(a[3])),
          "r"(__float_as_uint(b[0])), "r"(__float_as_uint(b[1])));
}

// ---------------------------------------------------------------------------
// mma.sync tf32 GEMM:  C[M,N] = alpha * A[M,K] @ B[N,K]^T (+ bias[N])
// SPLIT=true -> 3xTF32 (hi/lo decomposition, ~fp32 accuracy)
// TRANS_OUT=true -> C[N_idx, M_idx] with leading dim ldc
// Requires M % 128 == 0, K % 16 == 0.
//
// CTA: 256 threads / 8 warps; warp grid 2(m) x 4(n); warp tile 64x32.
// SMEM tiles padded to stride 20 floats -> conflict-free fragment LDS.
// Register-prefetch double buffering over BK=16 chunks.
// ---------------------------------------------------------------------------
template <bool SPLIT, bool TRANS_OUT>
__global__ void __launch_bounds__(256)
gemm_mma(const float* __restrict__ A, const float* __restrict__ B,
         const float* __restrict__ bias, float* __restrict__ C,
         int M, int N, int K, float alpha, int ldc, int causal)
{
    constexpr int BM = 128, BN = 128, BK = 16, SST = 20;   // SMEM row stride (floats)
    constexpr int TILE = BM * SST;                         // floats per tile
    constexpr int NB = SPLIT ? 4 : 2;                      // tiles per stage

    extern __shared__ float smem[];

    const int tid  = threadIdx.x;
    const int wid  = tid >> 5;
    const int lane = tid & 31;
    const int g    = lane >> 2;   // 0..7
    const int tg   = lane & 3;    // 0..3
    const int m0 = blockIdx.y * BM;
    const int n0 = blockIdx.x * BN;
    if (causal && n0 > m0 + BM - 1) return;   // fully masked upper-tri tile

    const int wm = (wid & 1) * 64;
    const int wn = (wid >> 1) * 32;

    // loader mapping: 2 float4 per thread per matrix per chunk
    const int lrow0 = tid >> 2;          // rows 0..63 (r=0), +64 (r=1)
    const int lcol  = (tid & 3) * 4;     // float4 col offset

    float acc[4][4][4];
#pragma unroll
    for (int mf = 0; mf < 4; ++mf)
#pragma unroll
        for (int nf = 0; nf < 4; ++nf)
#pragma unroll
            for (int r = 0; r < 4; ++r) acc[mf][nf][r] = 0.0f;

    const int nchunks = K / BK;
    float4 ra[2], rb[2];

    // ---- prologue: load chunk 0 ----
#pragma unroll
    for (int r = 0; r < 2; ++r) {
        const int row = lrow0 + r * 64;
        ra[r] = *reinterpret_cast<const float4*>(A + (size_t)(m0 + row) * K + lcol);
        const int gn = n0 + row;
        rb[r] = (gn < N) ? *reinterpret_cast<const float4*>(B + (size_t)gn * K + lcol)
                         : make_float4(0.f, 0.f, 0.f, 0.f);
    }
    {
        float* Ah = smem;                    // stage 0
        float* Bh = Ah + TILE;
        float* Al = Bh + TILE;
        float* Bl = Al + TILE;
#pragma unroll
        for (int r = 0; r < 2; ++r) {
            const int row = lrow0 + r * 64;
            float4 ah = tf32r4(ra[r]), bh = tf32r4(rb[r]);
            *reinterpret_cast<float4*>(Ah + row * SST + lcol) = ah;
            *reinterpret_cast<float4*>(Bh + row * SST + lcol) = bh;
            if (SPLIT) {
                *reinterpret_cast<float4*>(Al + row * SST + lcol) = tf32r4(sub4(ra[r], ah));
                *reinterpret_cast<float4*>(Bl + row * SST + lcol) = tf32r4(sub4(rb[r], bh));
            }
        }
    }
    __syncthreads();

    for (int i = 1; i <= nchunks; ++i) {
        // ---- prefetch chunk i (gmem -> regs), overlaps compute below ----
        if (i < nchunks) {
            const int k0 = i * BK;
#pragma unroll
            for (int r = 0; r < 2; ++r) {
                const int row = lrow0 + r * 64;
                ra[r] = *reinterpret_cast<const float4*>(A + (size_t)(m0 + row) * K + k0 + lcol);
                const int gn = n0 + row;
                rb[r] = (gn < N) ? *reinterpret_cast<const float4*>(B + (size_t)gn * K + k0 + lcol)
                                 : make_float4(0.f, 0.f, 0.f, 0.f);
            }
        }

        // ---- compute chunk i-1 from stage (i-1)&1 ----
        {
            float* st = smem + ((i - 1) & 1) * (NB * TILE);
            float* Ah = st;
            float* Bh = Ah + TILE;
            float* Al = Bh + TILE;
            float* Bl = Al + TILE;
            constexpr int NPASS = SPLIT ? 3 : 1;
#pragma unroll
            for (int ks = 0; ks < 2; ++ks) {
                const int kc = ks * 8 + tg;
#pragma unroll
                for (int p = 0; p < NPASS; ++p) {
                    const float* pa = (p == 2) ? Al : Ah;
                    const float* pb = (p == 1) ? Bl : Bh;
                    float afr[4][4];
#pragma unroll
                    for (int mf = 0; mf < 4; ++mf) {
                        const int ar = wm + mf * 16 + g;
                        afr[mf][0] = pa[ar * SST + kc];
                        afr[mf][1] = pa[(ar + 8) * SST + kc];
                        afr[mf][2] = pa[ar * SST + kc + 4];
                        afr[mf][3] = pa[(ar + 8) * SST + kc + 4];
                    }
#pragma unroll
                    for (int nf = 0; nf < 4; ++nf) {
                        const int br = wn + nf * 8 + g;
                        float bfr[2];
                        bfr[0] = pb[br * SST + kc];
                        bfr[1] = pb[br * SST + kc + 4];
#pragma unroll
                        for (int mf = 0; mf < 4; ++mf)
                            mma16n8k8(acc[mf][nf], afr[mf], bfr);
                    }
                }
            }
        }

        // ---- store chunk i to stage i&1 ----
        if (i < nchunks) {
            float* st = smem + (i & 1) * (NB * TILE);
            float* Ah = st;
            float* Bh = Ah + TILE;
            float* Al = Bh + TILE;
            float* Bl = Al + TILE;
#pragma unroll
            for (int r = 0; r < 2; ++r) {
                const int row = lrow0 + r * 64;
                float4 ah = tf32r4(ra[r]), bh = tf32r4(rb[r]);
                *reinterpret_cast<float4*>(Ah + row * SST + lcol) = ah;
                *reinterpret_cast<float4*>(Bh + row * SST + lcol) = bh;
                if (SPLIT) {
                    *reinterpret_cast<float4*>(Al + row * SST + lcol) = tf32r4(sub4(ra[r], ah));
                    *reinterpret_cast<float4*>(Bl + row * SST + lcol) = tf32r4(sub4(rb[r], bh));
                }
            }
            __syncthreads();
        }
    }

    // ---- epilogue (scalar stores: ldc may be odd, e.g. VOCAB=50257) ----
#pragma unroll
    for (int mf = 0; mf < 4; ++mf) {
#pragma unroll
        for (int half = 0; half < 2; ++half) {
            const int gm = m0 + wm + mf * 16 + g + half * 8;
#pragma unroll
            for (int nf = 0; nf < 4; ++nf) {
                const int gn = n0 + wn + nf * 8 + tg * 2;
                float v0 = acc[mf][nf][half * 2 + 0] * alpha;
                float v1 = acc[mf][nf][half * 2 + 1] * alpha;
                if (bias) {
                    if (gn < N)     v0 += bias[gn];
                    if (gn + 1 < N) v1 += bias[gn + 1];
                }
                if (TRANS_OUT) {
                    if (gn < N)     C[(size_t)gn * ldc + gm] = v0;
                    if (gn + 1 < N) C[(size_t)(gn + 1) * ldc + gm] = v1;
                } else {
                    if (gn < N)     C[(size_t)gm * ldc + gn]     = v0;
                    if (gn + 1 < N) C[(size_t)gm * ldc + gn + 1] = v1;
                }
            }
        }
    }
}

// ---------------------------------------------------------------------------
// Embedding gather
// ---------------------------------------------------------------------------
__global__ void gather_kernel(const int* __restrict__ tokens,
                              const float* __restrict__ E,
                              float* __restrict__ x) {
    int row = blockIdx.x;
    int t = tokens[row];
    const float4* src = reinterpret_cast<const float4*>(E + (size_t)t * DMODEL);
    float4* dst = reinterpret_cast<float4*>(x + (size_t)row * DMODEL);
    dst[threadIdx.x] = src[threadIdx.x];
}

// ---------------------------------------------------------------------------
// Causal row softmax in place
// ---------------------------------------------------------------------------
__global__ void softmax_causal_kernel(float* __restrict__ S) {
    const int row = blockIdx.x;
    float* s = S + (size_t)row * NTOK;
    const int len = row + 1;
    __shared__ float red[256];
    const int t = threadIdx.x;

    float m = -1e30f;
    for (int j = t; j < len; j += 256) m = fmaxf(m, s[j]);
    red[t] = m;
    __syncthreads();
#pragma unroll
    for (int st = 128; st > 0; st >>= 1) {
        if (t < st) red[t] = fmaxf(red[t], red[t + st]);
        __syncthreads();
    }
    m = red[0];
    __syncthreads();

    float sum = 0.0f;
    for (int j = t; j < len; j += 256) {
        const float e = expf(s[j] - m);
        s[j] = e;
        sum += e;
    }
    red[t] = sum;
    __syncthreads();
#pragma unroll
    for (int st = 128; st > 0; st >>= 1) {
        if (t < st) red[t] += red[t + st];
        __syncthreads();
    }
    const float inv = 1.0f / red[0];
    __syncthreads();

    for (int j = t; j < len; j += 256) s[j] *= inv;
    for (int j = len + t; j < NTOK; j += 256) s[j] = 0.0f;   // dense-GEMM tail
}

// ---------------------------------------------------------------------------
// Launch
// ---------------------------------------------------------------------------
extern "C" void kernel_launch(void* const* d_in, const int* in_sizes, int n_in,
                              void* d_out, int out_size) {
    const int*   tokens = (const int*)d_in[0];
    const float* E  = (const float*)d_in[1];
    const float* Wq = (const float*)d_in[2];
    const float* bq = (const float*)d_in[3];
    const float* Wk = (const float*)d_in[4];
    const float* bk = (const float*)d_in[5];
    const float* Wv = (const float*)d_in[6];
    const float* bv = (const float*)d_in[7];
    const float* Wp = (const float*)d_in[8];
    const float* bp = (const float*)d_in[9];
    float* out = (float*)d_out;

    float *x, *q, *k, *vt, *s, *o;
    cudaGetSymbolAddress((void**)&x,  g_x);
    cudaGetSymbolAddress((void**)&q,  g_q);
    cudaGetSymbolAddress((void**)&k,  g_k);
    cudaGetSymbolAddress((void**)&vt, g_vt);
    cudaGetSymbolAddress((void**)&s,  g_s);
    cudaGetSymbolAddress((void**)&o,  g_o);

    // SMEM: stride-20 tiles, BK=16, double buffered
    constexpr int SMEM_SPLIT = 2 * 4 * 128 * 20 * 4;   // 81920 B
    constexpr int SMEM_1P    = 2 * 2 * 128 * 20 * 4;   // 40960 B
    cudaFuncSetAttribute(gemm_mma<true, false>,  cudaFuncAttributeMaxDynamicSharedMemorySize, SMEM_SPLIT);
    cudaFuncSetAttribute(gemm_mma<true, true >,  cudaFuncAttributeMaxDynamicSharedMemorySize, SMEM_SPLIT);
    cudaFuncSetAttribute(gemm_mma<false, false>, cudaFuncAttributeMaxDynamicSharedMemorySize, SMEM_1P);

    const float inv_sqrt_d = 1.0f / 32.0f;

    gather_kernel<<<NTOK, 256>>>(tokens, E, x);

    // Q/K = x @ W^T + b ; V written transposed for the AV GEMM
    dim3 g1(DMODEL / 128, NTOK / 128);
    gemm_mma<true, false><<<g1, 256, SMEM_SPLIT>>>(x, Wq, bq, q,  NTOK, DMODEL, DMODEL, 1.0f, DMODEL, 0);
    gemm_mma<true, false><<<g1, 256, SMEM_SPLIT>>>(x, Wk, bk, k,  NTOK, DMODEL, DMODEL, 1.0f, DMODEL, 0);
    gemm_mma<true, true ><<<g1, 256, SMEM_SPLIT>>>(x, Wv, bv, vt, NTOK, DMODEL, DMODEL, 1.0f, NTOK,   0);

    // S = Q @ K^T / sqrt(d)  (skip fully-masked tiles)
    dim3 g2(NTOK / 128, NTOK / 128);
    gemm_mma<true, false><<<g2, 256, SMEM_SPLIT>>>(q, k, nullptr, s, NTOK, NTOK, DMODEL, inv_sqrt_d, NTOK, 1);

    softmax_causal_kernel<<<NTOK, 256>>>(s);

    // O = A @ V  (B = V^T, K-major)
    gemm_mma<true, false><<<g1, 256, SMEM_SPLIT>>>(s, vt, nullptr, o, NTOK, DMODEL, NTOK, 1.0f, DMODEL, 0);

    // logits = O @ Wp^T + bp  (1-pass rna-rounded tf32)
    dim3 g3((VOCAB + 127) / 128, NTOK / 128);
    gemm_mma<false, false><<<g3, 256, SMEM_1P>>>(o, Wp, bp, out, NTOK, VOCAB, DMODEL, 1.0f, VOCAB, 0);
}